// round 7
// baseline (speedup 1.0000x reference)
#include <cuda_runtime.h>
#include <math.h>

#define N_NODES 81
#define N_EDGES 1620
#define IN_DIM 10
#define HIDDEN 8192
#define ACTIONS 729
#define K7_BLOCKS (3 * 128)

// Scratch (__device__ globals; no allocation allowed)
__device__ float d_h2[N_NODES * HIDDEN];
__device__ float d_gacc[HIDDEN];
__device__ float d_t1[HIDDEN];
__device__ float d_logits[ACTIONS];
__device__ float d_dinv[N_NODES];
__device__ float d_nsum[N_NODES];
__device__ float d_nsq[N_NODES];
__device__ int   d_csr_src[N_EDGES];
__device__ float d_csr_w[N_EDGES];
__device__ int   d_off[N_NODES + 1];
__device__ int   d_ctr;

// ---------------------------------------------------------------------------
// K0: grid of 9 blocks. Block 0 builds CSR; all blocks zero accumulators.
__global__ void k0_prep(const int* __restrict__ edge) {
    int tid = threadIdx.x;
    int gi = blockIdx.x * 256 + tid;
    for (int i = gi; i < HIDDEN; i += 9 * 256) { d_t1[i] = 0.f; d_gacc[i] = 0.f; }
    for (int i = gi; i < ACTIONS; i += 9 * 256) d_logits[i] = 0.f;
    if (gi < N_NODES) { d_nsum[gi] = 0.f; d_nsq[gi] = 0.f; }
    if (gi == 0) d_ctr = 0;

    if (blockIdx.x != 0) return;
    __shared__ int cnt[N_NODES];
    __shared__ int off[N_NODES + 1];
    __shared__ float sdinv[N_NODES];
    for (int i = tid; i < N_NODES; i += blockDim.x) cnt[i] = 0;
    __syncthreads();
    for (int e = tid; e < N_EDGES; e += blockDim.x) {
        int d = edge[N_EDGES + e];
        if ((unsigned)d < N_NODES) atomicAdd(&cnt[d], 1);
    }
    __syncthreads();
    for (int i = tid; i < N_NODES; i += blockDim.x) {
        float dv = rsqrtf((float)(cnt[i] + 1));   // +1 self loop
        sdinv[i] = dv;
        d_dinv[i] = dv;
    }
    __syncthreads();
    if (tid == 0) {
        off[0] = 0;
        for (int i = 0; i < N_NODES; i++) off[i + 1] = off[i] + cnt[i];
    }
    __syncthreads();
    for (int i = tid; i <= N_NODES; i += blockDim.x) d_off[i] = off[i];
    for (int i = tid; i < N_NODES; i += blockDim.x) cnt[i] = off[i];  // scatter cursor
    __syncthreads();
    for (int e = tid; e < N_EDGES; e += blockDim.x) {
        int s = edge[e];
        int d = edge[N_EDGES + e];
        if ((unsigned)s < N_NODES && (unsigned)d < N_NODES) {
            int pos = atomicAdd(&cnt[d], 1);
            d_csr_src[pos] = s;
            d_csr_w[pos] = sdinv[s] * sdinv[d];
        }
    }
}

// ---------------------------------------------------------------------------
// K2: fused transform + aggregation + bias + relu + LN partial sums.
__global__ void __launch_bounds__(256) k2_agg(const float* __restrict__ x,
                                              const float* __restrict__ Wg,
                                              const float* __restrict__ bg) {
    __shared__ float sx[N_NODES * IN_DIM];
    __shared__ int   s_src[256];
    __shared__ float s_w[256];
    __shared__ float wsum[8], wsq[8];
    int tid = threadIdx.x;
    int n = blockIdx.y;
    int j = blockIdx.x * 256 + tid;

    for (int i = tid; i < N_NODES * IN_DIM; i += 256) sx[i] = x[i];
    float wreg[IN_DIM];
#pragma unroll
    for (int k = 0; k < IN_DIM; k++) wreg[k] = Wg[k * HIDDEN + j];
    __syncthreads();

    float dv = d_dinv[n];
    float hs = 0.f;
#pragma unroll
    for (int k = 0; k < IN_DIM; k++) hs += sx[n * IN_DIM + k] * wreg[k];
    float acc = hs * dv * dv;                        // self loop

    int beg = d_off[n], end = d_off[n + 1];
    for (int base = beg; base < end; base += 256) {
        int m = min(256, end - base);
        if (tid < m) { s_src[tid] = d_csr_src[base + tid]; s_w[tid] = d_csr_w[base + tid]; }
        __syncthreads();
        for (int i = 0; i < m; i++) {
            int s = s_src[i];
            float hv = 0.f;
#pragma unroll
            for (int k = 0; k < IN_DIM; k++) hv += sx[s * IN_DIM + k] * wreg[k];
            acc += hv * s_w[i];
        }
        __syncthreads();
    }
    float v = acc + bg[j];
    v = v > 0.f ? v : 0.f;
    d_h2[n * HIDDEN + j] = v;

    float v1 = v, v2 = v * v;
#pragma unroll
    for (int o = 16; o > 0; o >>= 1) {
        v1 += __shfl_down_sync(0xffffffffu, v1, o);
        v2 += __shfl_down_sync(0xffffffffu, v2, o);
    }
    int warp = tid >> 5, lane = tid & 31;
    if (lane == 0) { wsum[warp] = v1; wsq[warp] = v2; }
    __syncthreads();
    if (tid == 0) {
        float s1 = 0.f, s2 = 0.f;
#pragma unroll
        for (int w = 0; w < 8; w++) { s1 += wsum[w]; s2 += wsq[w]; }
        atomicAdd(&d_nsum[n], s1);
        atomicAdd(&d_nsq[n], s2);
    }
}

// ---------------------------------------------------------------------------
// K4: layernorm + pool partials, node-split. grid (32, 27).
__global__ void __launch_bounds__(256) k4_pool() {
    __shared__ float s_mu[3], s_rstd[3];
    int tid = threadIdx.x;
    int n0 = blockIdx.y * 3;
    if (tid < 3) {
        float mu = d_nsum[n0 + tid] * (1.f / HIDDEN);
        float var = d_nsq[n0 + tid] * (1.f / HIDDEN) - mu * mu;
        s_mu[tid] = mu;
        s_rstd[tid] = rsqrtf(var + 1e-5f);
    }
    __syncthreads();
    int j = blockIdx.x * 256 + tid;
    float acc = 0.f;
#pragma unroll
    for (int t = 0; t < 3; t++)
        acc += (d_h2[(n0 + t) * HIDDEN + j] - s_mu[t]) * s_rstd[t];
    atomicAdd(&d_gacc[j], acc);
}

// ---------------------------------------------------------------------------
// K6: split-K GEMV t1 += g @ W1. K-chunk=32 (grid 8x256 for smooth waves),
// explicit 8-deep load batches, streaming loads.
__global__ void __launch_bounds__(256, 4) k6_gemv1(const float* __restrict__ W1,
                                                   const float* __restrict__ lg,
                                                   const float* __restrict__ lb) {
    __shared__ float sg[32];
    int tid = threadIdx.x;
    int k0 = blockIdx.y * 32;
    if (tid < 32) {
        int k = k0 + tid;
        sg[tid] = lg[k] * d_gacc[k] + (float)N_NODES * lb[k];
    }
    __syncthreads();

    int ci = blockIdx.x * 256 + tid;                 // float4 column index
    const float4* base = reinterpret_cast<const float4*>(W1) + (size_t)k0 * (HIDDEN / 4) + ci;
    float4 acc = make_float4(0.f, 0.f, 0.f, 0.f);
#pragma unroll
    for (int k = 0; k < 32; k += 8) {
        float4 w[8];
#pragma unroll
        for (int u = 0; u < 8; u++)
            w[u] = __ldcs(base + (size_t)(k + u) * (HIDDEN / 4));
#pragma unroll
        for (int u = 0; u < 8; u++) {
            float gk = sg[k + u];
            acc.x += gk * w[u].x; acc.y += gk * w[u].y;
            acc.z += gk * w[u].z; acc.w += gk * w[u].w;
        }
    }
    int col = ci * 4;
    atomicAdd(&d_t1[col + 0], acc.x);
    atomicAdd(&d_t1[col + 1], acc.y);
    atomicAdd(&d_t1[col + 2], acc.z);
    atomicAdd(&d_t1[col + 3], acc.w);
}

// ---------------------------------------------------------------------------
// K7: logits += relu(t1 + b1) @ W2 (split-K), then the LAST block to finish
// performs log_softmax (fence + counter pattern).
__global__ void __launch_bounds__(256, 4) k7_gemv2(const float* __restrict__ W2,
                                                   const float* __restrict__ b1,
                                                   const float* __restrict__ b2,
                                                   float* __restrict__ out) {
    __shared__ float sa[64];
    __shared__ int isLast;
    int tid = threadIdx.x;
    int k0 = blockIdx.y * 64;
    if (tid < 64) {
        float a = d_t1[k0 + tid] + b1[k0 + tid];
        sa[tid] = a > 0.f ? a : 0.f;
    }
    __syncthreads();
    int j = blockIdx.x * 256 + tid;
    if (j < ACTIONS) {
        const float* base = W2 + (size_t)k0 * ACTIONS + j;
        float acc = 0.f;
#pragma unroll
        for (int k = 0; k < 64; k += 8) {
            float w[8];
#pragma unroll
            for (int u = 0; u < 8; u++)
                w[u] = __ldcs(base + (size_t)(k + u) * ACTIONS);
#pragma unroll
            for (int u = 0; u < 8; u++)
                acc += sa[k + u] * w[u];
        }
        atomicAdd(&d_logits[j], acc);
    }

    // completion counter: last block does the softmax epilogue
    __threadfence();
    __syncthreads();
    if (tid == 0) {
        int old = atomicAdd(&d_ctr, 1);
        isLast = (old == K7_BLOCKS - 1);
    }
    __syncthreads();
    if (!isLast) return;

    // log_softmax over 729 logits, 256 threads (3 elems each)
    __shared__ float red[256];
    float l[3];
    float lmax = -INFINITY;
#pragma unroll
    for (int t = 0; t < 3; t++) {
        int idx = tid + t * 256;
        l[t] = (idx < ACTIONS) ? __ldcg(&d_logits[idx]) + b2[idx] : -INFINITY;
        lmax = fmaxf(lmax, l[t]);
    }
    red[tid] = lmax;
    __syncthreads();
    for (int o = 128; o > 0; o >>= 1) {
        if (tid < o) red[tid] = fmaxf(red[tid], red[tid + o]);
        __syncthreads();
    }
    float mx = red[0];
    __syncthreads();
    float es = 0.f;
#pragma unroll
    for (int t = 0; t < 3; t++)
        if (tid + t * 256 < ACTIONS) es += expf(l[t] - mx);
    red[tid] = es;
    __syncthreads();
    for (int o = 128; o > 0; o >>= 1) {
        if (tid < o) red[tid] += red[tid + o];
        __syncthreads();
    }
    float lse = logf(red[0]);
#pragma unroll
    for (int t = 0; t < 3; t++) {
        int idx = tid + t * 256;
        if (idx < ACTIONS) out[idx] = l[t] - mx - lse;
    }
}

extern "C" void kernel_launch(void* const* d_in, const int* in_sizes, int n_in,
                              void* d_out, int out_size) {
    const float* x    = (const float*)d_in[0];
    const int*   edge = (const int*)d_in[1];
    const float* Wg   = (const float*)d_in[2];
    const float* bg   = (const float*)d_in[3];
    const float* lng  = (const float*)d_in[4];
    const float* lnb  = (const float*)d_in[5];
    const float* W1   = (const float*)d_in[6];
    const float* b1   = (const float*)d_in[7];
    const float* W2   = (const float*)d_in[8];
    const float* b2   = (const float*)d_in[9];
    float* out = (float*)d_out;

    k0_prep<<<9, 256>>>(edge);
    k2_agg<<<dim3(HIDDEN / 256, N_NODES), 256>>>(x, Wg, bg);
    k4_pool<<<dim3(HIDDEN / 256, 27), 256>>>();
    k6_gemv1<<<dim3(8, 256), 256>>>(W1, lng, lnb);
    k7_gemv2<<<dim3(3, 128), 256>>>(W2, b1, b2, out);
}

// round 8
// speedup vs baseline: 1.0680x; 1.0680x over previous
#include <cuda_runtime.h>
#include <math.h>

#define N_NODES 81
#define N_EDGES 1620
#define IN_DIM 10
#define HIDDEN 8192
#define ACTIONS 729
#define K7_BLOCKS (3 * 128)

// Scratch (__device__ globals; no allocation allowed)
__device__ float d_h2[N_NODES * HIDDEN];
__device__ float d_x2[N_NODES * IN_DIM];    // (A_norm @ x), incl. self loops
__device__ float d_gacc[HIDDEN];
__device__ float d_t1[HIDDEN];
__device__ float d_logits[ACTIONS];
__device__ float d_nsum[N_NODES];
__device__ float d_nsq[N_NODES];
__device__ int   d_ctr;

// ---------------------------------------------------------------------------
// KA: 9 blocks. All blocks zero accumulators; block 0 computes x2 = A_norm @ x.
__global__ void kA_prep(const int* __restrict__ edge, const float* __restrict__ x) {
    int tid = threadIdx.x;
    int gi = blockIdx.x * 256 + tid;
    for (int i = gi; i < HIDDEN; i += 9 * 256) { d_t1[i] = 0.f; d_gacc[i] = 0.f; }
    for (int i = gi; i < ACTIONS; i += 9 * 256) d_logits[i] = 0.f;
    if (gi < N_NODES) { d_nsum[gi] = 0.f; d_nsq[gi] = 0.f; }
    if (gi == 0) d_ctr = 0;

    if (blockIdx.x != 0) return;
    __shared__ int   cnt[N_NODES];
    __shared__ float sdinv[N_NODES];
    __shared__ float sx2[N_NODES * IN_DIM];
    for (int i = tid; i < N_NODES; i += 256) cnt[i] = 0;
    __syncthreads();
    for (int e = tid; e < N_EDGES; e += 256) {
        int d = edge[N_EDGES + e];
        if ((unsigned)d < N_NODES) atomicAdd(&cnt[d], 1);
    }
    __syncthreads();
    for (int i = tid; i < N_NODES; i += 256)
        sdinv[i] = rsqrtf((float)(cnt[i] + 1));   // +1 self loop
    __syncthreads();
    // self loops: x2[n,c] = dinv[n]^2 * x[n,c]
    for (int i = tid; i < N_NODES * IN_DIM; i += 256) {
        int n = i / IN_DIM;
        float dv = sdinv[n];
        sx2[i] = dv * dv * x[i];
    }
    __syncthreads();
    // edges: x2[d,:] += dinv[s]*dinv[d] * x[s,:]
    for (int e = tid; e < N_EDGES; e += 256) {
        int s = edge[e];
        int d = edge[N_EDGES + e];
        if ((unsigned)s < N_NODES && (unsigned)d < N_NODES) {
            float norm = sdinv[s] * sdinv[d];
#pragma unroll
            for (int c = 0; c < IN_DIM; c++)
                atomicAdd(&sx2[d * IN_DIM + c], norm * x[s * IN_DIM + c]);
        }
    }
    __syncthreads();
    for (int i = tid; i < N_NODES * IN_DIM; i += 256) d_x2[i] = sx2[i];
}

// ---------------------------------------------------------------------------
// KB: h2[n,:] = relu(x2[n] @ Wg + bg), plus LN partial sums.
// grid (8, 81), 256 threads, 4 cols/thread via float4.
__global__ void __launch_bounds__(256) kB_transform(const float* __restrict__ Wg,
                                                    const float* __restrict__ bg) {
    __shared__ float sx[IN_DIM];
    __shared__ float wsum[8], wsq[8];
    int tid = threadIdx.x;
    int n = blockIdx.y;
    int cj = blockIdx.x * 256 + tid;                 // float4 column index
    if (tid < IN_DIM) sx[tid] = d_x2[n * IN_DIM + tid];
    __syncthreads();

    const float4* Wv = reinterpret_cast<const float4*>(Wg);
    const float4* bv = reinterpret_cast<const float4*>(bg);
    float4 b = bv[cj];
    float4 acc = make_float4(b.x, b.y, b.z, b.w);
#pragma unroll
    for (int k = 0; k < IN_DIM; k++) {
        float xv = sx[k];
        float4 w = Wv[k * (HIDDEN / 4) + cj];
        acc.x += xv * w.x; acc.y += xv * w.y;
        acc.z += xv * w.z; acc.w += xv * w.w;
    }
    acc.x = acc.x > 0.f ? acc.x : 0.f;
    acc.y = acc.y > 0.f ? acc.y : 0.f;
    acc.z = acc.z > 0.f ? acc.z : 0.f;
    acc.w = acc.w > 0.f ? acc.w : 0.f;
    reinterpret_cast<float4*>(d_h2)[(size_t)n * (HIDDEN / 4) + cj] = acc;

    float v1 = acc.x + acc.y + acc.z + acc.w;
    float v2 = acc.x * acc.x + acc.y * acc.y + acc.z * acc.z + acc.w * acc.w;
#pragma unroll
    for (int o = 16; o > 0; o >>= 1) {
        v1 += __shfl_down_sync(0xffffffffu, v1, o);
        v2 += __shfl_down_sync(0xffffffffu, v2, o);
    }
    int warp = tid >> 5, lane = tid & 31;
    if (lane == 0) { wsum[warp] = v1; wsq[warp] = v2; }
    __syncthreads();
    if (tid == 0) {
        float s1 = 0.f, s2 = 0.f;
#pragma unroll
        for (int w = 0; w < 8; w++) { s1 += wsum[w]; s2 += wsq[w]; }
        atomicAdd(&d_nsum[n], s1);
        atomicAdd(&d_nsq[n], s2);
    }
}

// ---------------------------------------------------------------------------
// K4: layernorm + pool partials, node-split. grid (32, 27).
__global__ void __launch_bounds__(256) k4_pool() {
    __shared__ float s_mu[3], s_rstd[3];
    int tid = threadIdx.x;
    int n0 = blockIdx.y * 3;
    if (tid < 3) {
        float mu = d_nsum[n0 + tid] * (1.f / HIDDEN);
        float var = d_nsq[n0 + tid] * (1.f / HIDDEN) - mu * mu;
        s_mu[tid] = mu;
        s_rstd[tid] = rsqrtf(var + 1e-5f);
    }
    __syncthreads();
    int j = blockIdx.x * 256 + tid;
    float acc = 0.f;
#pragma unroll
    for (int t = 0; t < 3; t++)
        acc += (d_h2[(n0 + t) * HIDDEN + j] - s_mu[t]) * s_rstd[t];
    atomicAdd(&d_gacc[j], acc);
}

// ---------------------------------------------------------------------------
// K6: split-K GEMV t1 += g @ W1. K-chunk=64, grid (8,128), MLP-8 batches. (R6 best)
__global__ void __launch_bounds__(256, 4) k6_gemv1(const float* __restrict__ W1,
                                                   const float* __restrict__ lg,
                                                   const float* __restrict__ lb) {
    __shared__ float sg[64];
    int tid = threadIdx.x;
    int k0 = blockIdx.y * 64;
    if (tid < 64) {
        int k = k0 + tid;
        sg[tid] = lg[k] * d_gacc[k] + (float)N_NODES * lb[k];
    }
    __syncthreads();

    int ci = blockIdx.x * 256 + tid;
    const float4* base = reinterpret_cast<const float4*>(W1) + (size_t)k0 * (HIDDEN / 4) + ci;
    float4 acc = make_float4(0.f, 0.f, 0.f, 0.f);
#pragma unroll
    for (int k = 0; k < 64; k += 8) {
        float4 w[8];
#pragma unroll
        for (int u = 0; u < 8; u++)
            w[u] = __ldcs(base + (size_t)(k + u) * (HIDDEN / 4));
#pragma unroll
        for (int u = 0; u < 8; u++) {
            float gk = sg[k + u];
            acc.x += gk * w[u].x; acc.y += gk * w[u].y;
            acc.z += gk * w[u].z; acc.w += gk * w[u].w;
        }
    }
    int col = ci * 4;
    atomicAdd(&d_t1[col + 0], acc.x);
    atomicAdd(&d_t1[col + 1], acc.y);
    atomicAdd(&d_t1[col + 2], acc.z);
    atomicAdd(&d_t1[col + 3], acc.w);
}

// ---------------------------------------------------------------------------
// K7: logits += relu(t1 + b1) @ W2 (split-K); last block runs log_softmax.
__global__ void __launch_bounds__(256, 4) k7_gemv2(const float* __restrict__ W2,
                                                   const float* __restrict__ b1,
                                                   const float* __restrict__ b2,
                                                   float* __restrict__ out) {
    __shared__ float sa[64];
    __shared__ int isLast;
    int tid = threadIdx.x;
    int k0 = blockIdx.y * 64;
    if (tid < 64) {
        float a = d_t1[k0 + tid] + b1[k0 + tid];
        sa[tid] = a > 0.f ? a : 0.f;
    }
    __syncthreads();
    int j = blockIdx.x * 256 + tid;
    if (j < ACTIONS) {
        const float* base = W2 + (size_t)k0 * ACTIONS + j;
        float acc = 0.f;
#pragma unroll
        for (int k = 0; k < 64; k += 8) {
            float w[8];
#pragma unroll
            for (int u = 0; u < 8; u++)
                w[u] = __ldcs(base + (size_t)(k + u) * ACTIONS);
#pragma unroll
            for (int u = 0; u < 8; u++)
                acc += sa[k + u] * w[u];
        }
        atomicAdd(&d_logits[j], acc);
    }

    __threadfence();
    __syncthreads();
    if (tid == 0) {
        int old = atomicAdd(&d_ctr, 1);
        isLast = (old == K7_BLOCKS - 1);
    }
    __syncthreads();
    if (!isLast) return;

    __shared__ float red[256];
    float l[3];
    float lmax = -INFINITY;
#pragma unroll
    for (int t = 0; t < 3; t++) {
        int idx = tid + t * 256;
        l[t] = (idx < ACTIONS) ? __ldcg(&d_logits[idx]) + b2[idx] : -INFINITY;
        lmax = fmaxf(lmax, l[t]);
    }
    red[tid] = lmax;
    __syncthreads();
    for (int o = 128; o > 0; o >>= 1) {
        if (tid < o) red[tid] = fmaxf(red[tid], red[tid + o]);
        __syncthreads();
    }
    float mx = red[0];
    __syncthreads();
    float es = 0.f;
#pragma unroll
    for (int t = 0; t < 3; t++)
        if (tid + t * 256 < ACTIONS) es += expf(l[t] - mx);
    red[tid] = es;
    __syncthreads();
    for (int o = 128; o > 0; o >>= 1) {
        if (tid < o) red[tid] += red[tid + o];
        __syncthreads();
    }
    float lse = logf(red[0]);
#pragma unroll
    for (int t = 0; t < 3; t++) {
        int idx = tid + t * 256;
        if (idx < ACTIONS) out[idx] = l[t] - mx - lse;
    }
}

extern "C" void kernel_launch(void* const* d_in, const int* in_sizes, int n_in,
                              void* d_out, int out_size) {
    const float* x    = (const float*)d_in[0];
    const int*   edge = (const int*)d_in[1];
    const float* Wg   = (const float*)d_in[2];
    const float* bg   = (const float*)d_in[3];
    const float* lng  = (const float*)d_in[4];
    const float* lnb  = (const float*)d_in[5];
    const float* W1   = (const float*)d_in[6];
    const float* b1   = (const float*)d_in[7];
    const float* W2   = (const float*)d_in[8];
    const float* b2   = (const float*)d_in[9];
    float* out = (float*)d_out;

    kA_prep<<<9, 256>>>(edge, x);
    kB_transform<<<dim3(HIDDEN / 1024, N_NODES), 256>>>(Wg, bg);
    k4_pool<<<dim3(HIDDEN / 256, 27), 256>>>();
    k6_gemv1<<<dim3(8, 128), 256>>>(W1, lng, lnb);
    k7_gemv2<<<dim3(3, 128), 256>>>(W2, b1, b2, out);
}